// round 2
// baseline (speedup 1.0000x reference)
#include <cuda_runtime.h>
#include <math.h>

#define NN   81920      // nodes
#define HCC  64         // hidden channels
#define EE   1310720    // edges
#define BSZ  512        // batch (graphs)
#define NG   5
#define NEL  32
#define NCLS 3

// Scratch (static device globals — allocation-free per harness rules)
__device__ float g_h[NN * HCC];     // node state
__device__ float g_m[NN * HCC];     // h @ Wg
__device__ float g_aggr[NN * HCC];  // scatter-add target
__device__ float g_z1[BSZ * HCC];   // MLP layer-1 activations

// ---------------------------------------------------------------------------
// K0: h = pad(x, HC)   (x is [N,5])
// ---------------------------------------------------------------------------
__global__ void k_init(const float* __restrict__ x) {
    int idx = blockIdx.x * blockDim.x + threadIdx.x;
    if (idx >= NN * HCC) return;
    int n = idx >> 6, k = idx & 63;
    g_h[idx] = (k < 5) ? x[n * 5 + k] : 0.0f;
}

// ---------------------------------------------------------------------------
// K1: m = h @ Wg[layer]  (64x64), also zero aggr.
// One warp per node row; Wg staged in smem; broadcast h via shfl.
// ---------------------------------------------------------------------------
__global__ void k_matmul(const float* __restrict__ Wg) {
    __shared__ float Ws[64 * 64];
    int tid = threadIdx.x;
    for (int i = tid; i < 4096; i += 256) Ws[i] = Wg[i];
    __syncthreads();

    int lane = tid & 31, w = tid >> 5;
    int n = blockIdx.x * 8 + w;
    float h0 = g_h[n * 64 + lane];
    float h1 = g_h[n * 64 + 32 + lane];
    float a0 = 0.f, a1 = 0.f;
#pragma unroll
    for (int k = 0; k < 32; k++) {
        float hv = __shfl_sync(0xffffffffu, h0, k);
        a0 += hv * Ws[k * 64 + lane];
        a1 += hv * Ws[k * 64 + 32 + lane];
    }
#pragma unroll
    for (int k = 0; k < 32; k++) {
        float hv = __shfl_sync(0xffffffffu, h1, k);
        a0 += hv * Ws[(k + 32) * 64 + lane];
        a1 += hv * Ws[(k + 32) * 64 + 32 + lane];
    }
    g_m[n * 64 + lane] = a0;
    g_m[n * 64 + 32 + lane] = a1;
    g_aggr[n * 64 + lane] = 0.f;
    g_aggr[n * 64 + 32 + lane] = 0.f;
}

// ---------------------------------------------------------------------------
// K2: edge scatter: aggr[dst] += m[src] * ea[e]
// 16 threads per edge, float4 per thread, vectorized L2 reduction.
// ---------------------------------------------------------------------------
__global__ void k_scatter(const int* __restrict__ ei, const float* __restrict__ ea) {
    int t = blockIdx.x * blockDim.x + threadIdx.x;  // < EE*16
    int e = t >> 4, q = t & 15;
    int src = ei[e];
    int dst = ei[EE + e];
    float w = ea[e];
    float4 v = reinterpret_cast<const float4*>(g_m)[src * 16 + q];
    float vx = v.x * w, vy = v.y * w, vz = v.z * w, vw = v.w * w;
    float* p = &g_aggr[dst * 64 + q * 4];
    asm volatile("red.global.add.v4.f32 [%0], {%1,%2,%3,%4};"
                 :: "l"(p), "f"(vx), "f"(vy), "f"(vz), "f"(vw)
                 : "memory");
}

// ---------------------------------------------------------------------------
// K3: fused GRU cell. One warp handles 2 node rows; lane owns features
// f0=lane, f1=lane+32 of all three gates for both gi and gh, so gate math
// needs no cross-lane traffic. Weights transposed into smem with stride 193
// (bank-conflict-free for both the transpose stores and compute loads).
// ---------------------------------------------------------------------------
#define WSTRIDE 193

__device__ __forceinline__ void gru_accum(
    const float* __restrict__ WI, const float* __restrict__ WH,
    int lane, int koff,
    float a0, float a1, float h0, float h1,
    float ir[2][2], float iz[2][2], float inn[2][2],
    float hr[2][2], float hz[2][2], float hn[2][2])
{
#pragma unroll 4
    for (int k = 0; k < 32; k++) {
        float av[2], hv[2];
        av[0] = __shfl_sync(0xffffffffu, a0, k);
        av[1] = __shfl_sync(0xffffffffu, a1, k);
        hv[0] = __shfl_sync(0xffffffffu, h0, k);
        hv[1] = __shfl_sync(0xffffffffu, h1, k);
        const float* wi = WI + (koff + k) * WSTRIDE;
        const float* wh = WH + (koff + k) * WSTRIDE;
#pragma unroll
        for (int g = 0; g < 2; g++) {
            float wr = wi[lane + g * 32];
            float wz = wi[lane + 64 + g * 32];
            float wn = wi[lane + 128 + g * 32];
            float vr = wh[lane + g * 32];
            float vz = wh[lane + 64 + g * 32];
            float vn = wh[lane + 128 + g * 32];
#pragma unroll
            for (int r = 0; r < 2; r++) {
                ir[r][g]  += av[r] * wr;
                iz[r][g]  += av[r] * wz;
                inn[r][g] += av[r] * wn;
                hr[r][g]  += hv[r] * vr;
                hz[r][g]  += hv[r] * vz;
                hn[r][g]  += hv[r] * vn;
            }
        }
    }
}

__global__ void k_gru(const float* __restrict__ w_ih, const float* __restrict__ w_hh,
                      const float* __restrict__ b_ih, const float* __restrict__ b_hh) {
    extern __shared__ float s[];
    float* WI = s;                       // [64][193]
    float* WH = s + 64 * WSTRIDE;        // [64][193]
    float* BI = WH + 64 * WSTRIDE;       // [192]
    float* BH = BI + 192;                // [192]

    int tid = threadIdx.x;
    for (int i = tid; i < 192 * 64; i += 512) {
        int j = i >> 6, k = i & 63;
        WI[k * WSTRIDE + j] = w_ih[i];
        WH[k * WSTRIDE + j] = w_hh[i];
    }
    for (int i = tid; i < 192; i += 512) { BI[i] = b_ih[i]; BH[i] = b_hh[i]; }
    __syncthreads();

    int lane = tid & 31, wp = tid >> 5;
    int n0 = (blockIdx.x * 16 + wp) * 2;
    int n1 = n0 + 1;

    float A00 = g_aggr[n0 * 64 + lane],      A01 = g_aggr[n0 * 64 + 32 + lane];
    float A10 = g_aggr[n1 * 64 + lane],      A11 = g_aggr[n1 * 64 + 32 + lane];
    float H00 = g_h[n0 * 64 + lane],         H01 = g_h[n0 * 64 + 32 + lane];
    float H10 = g_h[n1 * 64 + lane],         H11 = g_h[n1 * 64 + 32 + lane];

    float ir[2][2], iz[2][2], inn[2][2], hr[2][2], hz[2][2], hn[2][2];
#pragma unroll
    for (int r = 0; r < 2; r++) {
        ir[r][0]  = BI[lane];        ir[r][1]  = BI[lane + 32];
        iz[r][0]  = BI[64 + lane];   iz[r][1]  = BI[96 + lane];
        inn[r][0] = BI[128 + lane];  inn[r][1] = BI[160 + lane];
        hr[r][0]  = BH[lane];        hr[r][1]  = BH[lane + 32];
        hz[r][0]  = BH[64 + lane];   hz[r][1]  = BH[96 + lane];
        hn[r][0]  = BH[128 + lane];  hn[r][1]  = BH[160 + lane];
    }

    gru_accum(WI, WH, lane, 0,  A00, A10, H00, H10, ir, iz, inn, hr, hz, hn);
    gru_accum(WI, WH, lane, 32, A01, A11, H01, H11, ir, iz, inn, hr, hz, hn);

    float Hold[2][2] = { {H00, H01}, {H10, H11} };
    int nn[2] = { n0, n1 };
#pragma unroll
    for (int r = 0; r < 2; r++) {
#pragma unroll
        for (int g = 0; g < 2; g++) {
            float rg = 1.f / (1.f + expf(-(ir[r][g] + hr[r][g])));
            float zg = 1.f / (1.f + expf(-(iz[r][g] + hz[r][g])));
            float ng = tanhf(inn[r][g] + rg * hn[r][g]);
            g_h[nn[r] * 64 + g * 32 + lane] = (1.f - zg) * ng + zg * Hold[r][g];
        }
    }
}

// ---------------------------------------------------------------------------
// K4: z1 = relu(hperm @ W1^T + b1). hperm[bs, (e*G+g)*HC+f] = h[bs,g,e,f].
// Block handles 4 batch rows; K staged in 128-chunks; W1 smem padded (65).
// ---------------------------------------------------------------------------
__global__ void k_mlp1(const float* __restrict__ W1, const float* __restrict__ b1) {
    __shared__ float W1s[128 * 65];
    __shared__ float hs[4 * 128];
    int tid = threadIdx.x;
    int bs0 = blockIdx.x * 4;
    int b_l = tid >> 6, o = tid & 63;
    float acc = 0.f;

    for (int kb = 0; kb < NG * NEL * HCC; kb += 128) {
        __syncthreads();
        for (int i = tid; i < 64 * 128; i += 256) {
            int ol = i >> 7, kl = i & 127;
            W1s[kl * 65 + ol] = W1[(size_t)ol * (NG * NEL * HCC) + kb + kl];
        }
        for (int i = tid; i < 4 * 128; i += 256) {
            int bl = i >> 7, kl = i & 127;
            int in = kb + kl;
            int f = in & 63;
            int t2 = in >> 6;
            int g = t2 % NG, e = t2 / NG;
            hs[bl * 128 + kl] = g_h[((((bs0 + bl) * NG + g) * NEL + e) * HCC) + f];
        }
        __syncthreads();
#pragma unroll 8
        for (int kk = 0; kk < 128; kk++)
            acc += W1s[kk * 65 + o] * hs[b_l * 128 + kk];
    }
    acc += b1[o];
    g_z1[(bs0 + b_l) * 64 + o] = fmaxf(acc, 0.f);
}

// ---------------------------------------------------------------------------
// K5: tail MLP (64->32->16->3) + softmax. One warp per batch row.
// ---------------------------------------------------------------------------
__global__ void k_tail(const float* __restrict__ W2, const float* __restrict__ b2,
                       const float* __restrict__ W3, const float* __restrict__ b3,
                       const float* __restrict__ W4, const float* __restrict__ b4,
                       float* __restrict__ out) {
    __shared__ float W2s[64 * 32], W3s[32 * 16], W4s[16 * 3];
    __shared__ float b2s[32], b3s[16], b4s[3];
    int tid = threadIdx.x;
    for (int i = tid; i < 32 * 64; i += 256) { int o = i >> 6, k = i & 63; W2s[k * 32 + o] = W2[i]; }
    for (int i = tid; i < 16 * 32; i += 256) { int o = i >> 5, k = i & 31; W3s[k * 16 + o] = W3[i]; }
    for (int i = tid; i < 3 * 16;  i += 256) { int o = i >> 4, k = i & 15; W4s[k * 3 + o] = W4[i]; }
    if (tid < 32) b2s[tid] = b2[tid];
    if (tid < 16) b3s[tid] = b3[tid];
    if (tid < 3)  b4s[tid] = b4[tid];
    __syncthreads();

    int lane = tid & 31, wp = tid >> 5;
    int bs = blockIdx.x * 8 + wp;
    float l0 = g_z1[bs * 64 + lane];
    float l1 = g_z1[bs * 64 + 32 + lane];

    float acc2 = b2s[lane];
#pragma unroll
    for (int i = 0; i < 32; i++) acc2 += __shfl_sync(0xffffffffu, l0, i) * W2s[i * 32 + lane];
#pragma unroll
    for (int i = 0; i < 32; i++) acc2 += __shfl_sync(0xffffffffu, l1, i) * W2s[(i + 32) * 32 + lane];
    float z2 = fmaxf(acc2, 0.f);

    float acc3 = (lane < 16) ? b3s[lane] : 0.f;
#pragma unroll
    for (int i = 0; i < 32; i++) {
        float v = __shfl_sync(0xffffffffu, z2, i);
        if (lane < 16) acc3 += v * W3s[i * 16 + lane];
    }
    float z3 = fmaxf(acc3, 0.f);

    float accL = (lane < 3) ? b4s[lane] : 0.f;
#pragma unroll
    for (int i = 0; i < 16; i++) {
        float v = __shfl_sync(0xffffffffu, z3, i);
        if (lane < 3) accL += v * W4s[i * 3 + lane];
    }

    float L0 = __shfl_sync(0xffffffffu, accL, 0);
    float L1 = __shfl_sync(0xffffffffu, accL, 1);
    float L2 = __shfl_sync(0xffffffffu, accL, 2);
    float mx = fmaxf(L0, fmaxf(L1, L2));
    float e0 = expf(L0 - mx), e1 = expf(L1 - mx), e2 = expf(L2 - mx);
    float si = 1.f / (e0 + e1 + e2);
    if (lane == 0) {
        out[bs * 3 + 0] = e0 * si;
        out[bs * 3 + 1] = e1 * si;
        out[bs * 3 + 2] = e2 * si;
    }
}

// ---------------------------------------------------------------------------
extern "C" void kernel_launch(void* const* d_in, const int* in_sizes, int n_in,
                              void* d_out, int out_size) {
    const float* x     = (const float*)d_in[0];
    const int*   ei    = (const int*)  d_in[1];
    const float* ea    = (const float*)d_in[2];
    const float* Wg    = (const float*)d_in[3];
    const float* w_ih  = (const float*)d_in[4];
    const float* w_hh  = (const float*)d_in[5];
    const float* b_ih  = (const float*)d_in[6];
    const float* b_hh  = (const float*)d_in[7];
    const float* W1    = (const float*)d_in[8];
    const float* b1    = (const float*)d_in[9];
    const float* W2    = (const float*)d_in[10];
    const float* b2    = (const float*)d_in[11];
    const float* W3    = (const float*)d_in[12];
    const float* b3    = (const float*)d_in[13];
    const float* W4    = (const float*)d_in[14];
    const float* b4    = (const float*)d_in[15];
    float* out = (float*)d_out;

    const size_t gru_smem = (size_t)(2 * 64 * WSTRIDE + 2 * 192) * sizeof(float);
    cudaFuncSetAttribute(k_gru, cudaFuncAttributeMaxDynamicSharedMemorySize, (int)gru_smem);

    k_init<<<NN * HCC / 256, 256>>>(x);
    for (int layer = 0; layer < 2; layer++) {
        k_matmul<<<NN / 8, 256>>>(Wg + layer * HCC * HCC);
        k_scatter<<<(EE * 16) / 256, 256>>>(ei, ea);
        k_gru<<<NN / 32, 512, gru_smem>>>(w_ih, w_hh, b_ih, b_hh);
    }
    k_mlp1<<<BSZ / 4, 256>>>(W1, b1);
    k_tail<<<BSZ / 8, 256>>>(W2, b2, W3, b3, W4, b4, out);
}

// round 3
// speedup vs baseline: 1.0996x; 1.0996x over previous
#include <cuda_runtime.h>
#include <math.h>

#define NN   81920      // nodes
#define HCC  64         // hidden channels
#define EE   1310720    // edges
#define BSZ  512        // batch (graphs)
#define NG   5
#define NEL  32
#define NCLS 3

// Scratch (static device globals — allocation-free per harness rules)
__device__ float g_h[NN * HCC];       // node state
__device__ float g_m[NN * HCC];       // h @ Wg
__device__ float g_aggr[NN * HCC];    // gather target
__device__ float g_z1[BSZ * HCC];     // MLP layer-1 activations
__device__ int   g_deg[NN];
__device__ int   g_rowptr[NN + 1];
__device__ int   g_cursor[NN];
__device__ int   g_bsum[80];
__device__ int   g_csr_src[EE];
__device__ float g_csr_w[EE];

// ---- f32x2 packed helpers ------------------------------------------------
__device__ __forceinline__ unsigned long long pk2(float x, float y) {
    unsigned long long r;
    asm("mov.b64 %0, {%1, %2};" : "=l"(r) : "f"(x), "f"(y));
    return r;
}
__device__ __forceinline__ void unpk2(unsigned long long v, float& x, float& y) {
    asm("mov.b64 {%0, %1}, %2;" : "=f"(x), "=f"(y) : "l"(v));
}
__device__ __forceinline__ unsigned long long fma2(unsigned long long a,
                                                   unsigned long long b,
                                                   unsigned long long c) {
    unsigned long long d;
    asm("fma.rn.f32x2 %0, %1, %2, %3;" : "=l"(d) : "l"(a), "l"(b), "l"(c));
    return d;
}

// ---------------------------------------------------------------------------
// K0: h = pad(x, HC)   (x is [N,5])
// ---------------------------------------------------------------------------
__global__ void k_init(const float* __restrict__ x) {
    int idx = blockIdx.x * blockDim.x + threadIdx.x;
    if (idx >= NN * HCC) return;
    int n = idx >> 6, k = idx & 63;
    g_h[idx] = (k < 5) ? x[n * 5 + k] : 0.0f;
}

// ---------------------------------------------------------------------------
// CSR build: degree histogram -> exclusive scan -> fill
// ---------------------------------------------------------------------------
__global__ void k_zero_deg() {
    int i = blockIdx.x * blockDim.x + threadIdx.x;
    if (i < NN) g_deg[i] = 0;
}

__global__ void k_count(const int* __restrict__ ei) {
    int t = blockIdx.x * blockDim.x + threadIdx.x;
    if (t < EE) atomicAdd(&g_deg[ei[EE + t]], 1);
}

__global__ void k_scan1() {
    __shared__ int ws[32];
    int tid = threadIdx.x, lane = tid & 31, wid = tid >> 5;
    int i = blockIdx.x * 1024 + tid;
    int v = g_deg[i];
    int x = v;
#pragma unroll
    for (int d = 1; d < 32; d <<= 1) {
        int y = __shfl_up_sync(0xffffffffu, x, d);
        if (lane >= d) x += y;
    }
    if (lane == 31) ws[wid] = x;
    __syncthreads();
    if (wid == 0) {
        int s = ws[lane];
#pragma unroll
        for (int d = 1; d < 32; d <<= 1) {
            int y = __shfl_up_sync(0xffffffffu, s, d);
            if (lane >= d) s += y;
        }
        ws[lane] = s;
    }
    __syncthreads();
    int base = (wid > 0) ? ws[wid - 1] : 0;
    g_rowptr[i] = base + x - v;                      // exclusive within block
    if (tid == 1023) g_bsum[blockIdx.x] = base + x;  // block total
}

__global__ void k_scan2() {
    if (threadIdx.x == 0) {
        int run = 0;
        for (int b = 0; b < 80; b++) {
            int t = g_bsum[b];
            g_bsum[b] = run;
            run += t;
        }
        g_rowptr[NN] = run;
    }
}

__global__ void k_scan3() {
    int i = blockIdx.x * blockDim.x + threadIdx.x;
    if (i < NN) {
        int v = g_rowptr[i] + g_bsum[i >> 10];
        g_rowptr[i] = v;
        g_cursor[i] = v;
    }
}

__global__ void k_fill(const int* __restrict__ ei, const float* __restrict__ ea) {
    int t = blockIdx.x * blockDim.x + threadIdx.x;
    if (t >= EE) return;
    int d = ei[EE + t];
    int p = atomicAdd(&g_cursor[d], 1);
    g_csr_src[p] = ei[t];
    g_csr_w[p]   = ea[t];
}

// ---------------------------------------------------------------------------
// K1: m = h @ Wg[layer]. Warp handles 4 nodes; Wg in smem as float2 pairs
// {Wg[k][lane], Wg[k][lane+32]}; FFMA2 packed over the two output halves.
// ---------------------------------------------------------------------------
#define MP 33   // float2 stride per k (padded)

__global__ void k_matmul(const float* __restrict__ Wg) {
    __shared__ float Ws[64 * MP * 2];
    int tid = threadIdx.x;
    for (int i = tid; i < 4096; i += 256) {
        int k = i >> 6, o = i & 63;
        Ws[(k * MP + (o & 31)) * 2 + (o >> 5)] = Wg[k * 64 + o];
    }
    __syncthreads();
    const unsigned long long* Wu = (const unsigned long long*)Ws;

    int lane = tid & 31, wp = tid >> 5;
    int nb = (blockIdx.x * 8 + wp) * 4;

    float hA[4], hB[4];
#pragma unroll
    for (int r = 0; r < 4; r++) {
        hA[r] = g_h[(nb + r) * 64 + lane];
        hB[r] = g_h[(nb + r) * 64 + 32 + lane];
    }
    unsigned long long acc[4];
#pragma unroll
    for (int r = 0; r < 4; r++) acc[r] = 0ull;

#pragma unroll 4
    for (int k = 0; k < 32; k++) {
        unsigned long long w = Wu[k * MP + lane];
#pragma unroll
        for (int r = 0; r < 4; r++) {
            float hv = __shfl_sync(0xffffffffu, hA[r], k);
            acc[r] = fma2(w, pk2(hv, hv), acc[r]);
        }
    }
#pragma unroll 4
    for (int k = 0; k < 32; k++) {
        unsigned long long w = Wu[(k + 32) * MP + lane];
#pragma unroll
        for (int r = 0; r < 4; r++) {
            float hv = __shfl_sync(0xffffffffu, hB[r], k);
            acc[r] = fma2(w, pk2(hv, hv), acc[r]);
        }
    }
#pragma unroll
    for (int r = 0; r < 4; r++) {
        float a0, a1;
        unpk2(acc[r], a0, a1);
        g_m[(nb + r) * 64 + lane] = a0;
        g_m[(nb + r) * 64 + 32 + lane] = a1;
    }
}

// ---------------------------------------------------------------------------
// K2: CSR gather: aggr[n] = sum_e w_e * m[src_e]. Warp per node, no atomics.
// ---------------------------------------------------------------------------
__global__ void k_gather() {
    int lane = threadIdx.x & 31, wp = threadIdx.x >> 5;
    int n = blockIdx.x * 8 + wp;
    int beg = g_rowptr[n], end = g_rowptr[n + 1];
    float a0 = 0.f, a1 = 0.f;
    int e = beg;
    for (; e + 4 <= end; e += 4) {
        int   s0 = g_csr_src[e],     s1 = g_csr_src[e + 1];
        int   s2 = g_csr_src[e + 2], s3 = g_csr_src[e + 3];
        float w0 = g_csr_w[e],       w1 = g_csr_w[e + 1];
        float w2 = g_csr_w[e + 2],   w3 = g_csr_w[e + 3];
        float p00 = g_m[s0 * 64 + lane],      p01 = g_m[s0 * 64 + 32 + lane];
        float p10 = g_m[s1 * 64 + lane],      p11 = g_m[s1 * 64 + 32 + lane];
        float p20 = g_m[s2 * 64 + lane],      p21 = g_m[s2 * 64 + 32 + lane];
        float p30 = g_m[s3 * 64 + lane],      p31 = g_m[s3 * 64 + 32 + lane];
        a0 = fmaf(p00, w0, a0); a1 = fmaf(p01, w0, a1);
        a0 = fmaf(p10, w1, a0); a1 = fmaf(p11, w1, a1);
        a0 = fmaf(p20, w2, a0); a1 = fmaf(p21, w2, a1);
        a0 = fmaf(p30, w3, a0); a1 = fmaf(p31, w3, a1);
    }
    for (; e < end; e++) {
        int s = g_csr_src[e];
        float w = g_csr_w[e];
        a0 = fmaf(g_m[s * 64 + lane], w, a0);
        a1 = fmaf(g_m[s * 64 + 32 + lane], w, a1);
    }
    g_aggr[n * 64 + lane] = a0;
    g_aggr[n * 64 + 32 + lane] = a1;
}

// ---------------------------------------------------------------------------
// K3: fused GRU. Warp handles 4 nodes; accumulators packed f32x2 over the two
// output halves (o=lane, o=lane+32); weights in smem as float2 pairs so one
// LDS.64 feeds one FFMA2 per row.
// ---------------------------------------------------------------------------
#define KP 97   // float2 stride per k (padded)

__global__ __launch_bounds__(512) void k_gru(
        const float* __restrict__ w_ih, const float* __restrict__ w_hh,
        const float* __restrict__ b_ih, const float* __restrict__ b_hh) {
    extern __shared__ float s[];
    float* WI = s;                      // 64*KP float2
    float* WH = WI + 64 * KP * 2;
    float* BI = WH + 64 * KP * 2;       // 96 float2
    float* BH = BI + 192;

    int tid = threadIdx.x;
    for (int i = tid; i < 192 * 64; i += 512) {
        int o = i >> 6, k = i & 63;
        int gate = o >> 6, rem = o & 63, half = rem >> 5, ln = rem & 31;
        int d = (k * KP + gate * 32 + ln) * 2 + half;
        WI[d] = w_ih[i];
        WH[d] = w_hh[i];
    }
    if (tid < 96) {
        int gate = tid >> 5, ln = tid & 31;
        BI[tid * 2]     = b_ih[gate * 64 + ln];
        BI[tid * 2 + 1] = b_ih[gate * 64 + 32 + ln];
        BH[tid * 2]     = b_hh[gate * 64 + ln];
        BH[tid * 2 + 1] = b_hh[gate * 64 + 32 + ln];
    }
    __syncthreads();

    const unsigned long long* WIu = (const unsigned long long*)WI;
    const unsigned long long* WHu = (const unsigned long long*)WH;
    const unsigned long long* BIu = (const unsigned long long*)BI;
    const unsigned long long* BHu = (const unsigned long long*)BH;

    int lane = tid & 31, wp = tid >> 5;
    int nb = (blockIdx.x * 16 + wp) * 4;

    float aA[4], aB[4], hA[4], hB[4];
#pragma unroll
    for (int r = 0; r < 4; r++) {
        int n = nb + r;
        aA[r] = g_aggr[n * 64 + lane];
        aB[r] = g_aggr[n * 64 + 32 + lane];
        hA[r] = g_h[n * 64 + lane];
        hB[r] = g_h[n * 64 + 32 + lane];
    }

    unsigned long long IR[4], IZ[4], IN[4], HR[4], HZ[4], HN[4];
    {
        unsigned long long bir = BIu[lane], biz = BIu[32 + lane], bin = BIu[64 + lane];
        unsigned long long bhr = BHu[lane], bhz = BHu[32 + lane], bhn = BHu[64 + lane];
#pragma unroll
        for (int r = 0; r < 4; r++) {
            IR[r] = bir; IZ[r] = biz; IN[r] = bin;
            HR[r] = bhr; HZ[r] = bhz; HN[r] = bhn;
        }
    }

#pragma unroll 4
    for (int k = 0; k < 32; k++) {
        unsigned long long wir = WIu[k * KP + lane];
        unsigned long long wiz = WIu[k * KP + 32 + lane];
        unsigned long long win = WIu[k * KP + 64 + lane];
        unsigned long long whr = WHu[k * KP + lane];
        unsigned long long whz = WHu[k * KP + 32 + lane];
        unsigned long long whn = WHu[k * KP + 64 + lane];
#pragma unroll
        for (int r = 0; r < 4; r++) {
            float av = __shfl_sync(0xffffffffu, aA[r], k);
            float hv = __shfl_sync(0xffffffffu, hA[r], k);
            unsigned long long AV = pk2(av, av);
            unsigned long long HV = pk2(hv, hv);
            IR[r] = fma2(wir, AV, IR[r]);
            IZ[r] = fma2(wiz, AV, IZ[r]);
            IN[r] = fma2(win, AV, IN[r]);
            HR[r] = fma2(whr, HV, HR[r]);
            HZ[r] = fma2(whz, HV, HZ[r]);
            HN[r] = fma2(whn, HV, HN[r]);
        }
    }
#pragma unroll 4
    for (int k = 0; k < 32; k++) {
        int kk = k + 32;
        unsigned long long wir = WIu[kk * KP + lane];
        unsigned long long wiz = WIu[kk * KP + 32 + lane];
        unsigned long long win = WIu[kk * KP + 64 + lane];
        unsigned long long whr = WHu[kk * KP + lane];
        unsigned long long whz = WHu[kk * KP + 32 + lane];
        unsigned long long whn = WHu[kk * KP + 64 + lane];
#pragma unroll
        for (int r = 0; r < 4; r++) {
            float av = __shfl_sync(0xffffffffu, aB[r], k);
            float hv = __shfl_sync(0xffffffffu, hB[r], k);
            unsigned long long AV = pk2(av, av);
            unsigned long long HV = pk2(hv, hv);
            IR[r] = fma2(wir, AV, IR[r]);
            IZ[r] = fma2(wiz, AV, IZ[r]);
            IN[r] = fma2(win, AV, IN[r]);
            HR[r] = fma2(whr, HV, HR[r]);
            HZ[r] = fma2(whz, HV, HZ[r]);
            HN[r] = fma2(whn, HV, HN[r]);
        }
    }

#pragma unroll
    for (int r = 0; r < 4; r++) {
        int n = nb + r;
        float ir0, ir1, iz0, iz1, in0, in1, hr0, hr1, hz0, hz1, hn0, hn1;
        unpk2(IR[r], ir0, ir1); unpk2(IZ[r], iz0, iz1); unpk2(IN[r], in0, in1);
        unpk2(HR[r], hr0, hr1); unpk2(HZ[r], hz0, hz1); unpk2(HN[r], hn0, hn1);

        float rg0 = 1.f / (1.f + expf(-(ir0 + hr0)));
        float zg0 = 1.f / (1.f + expf(-(iz0 + hz0)));
        float ng0 = tanhf(in0 + rg0 * hn0);
        g_h[n * 64 + lane] = (1.f - zg0) * ng0 + zg0 * hA[r];

        float rg1 = 1.f / (1.f + expf(-(ir1 + hr1)));
        float zg1 = 1.f / (1.f + expf(-(iz1 + hz1)));
        float ng1 = tanhf(in1 + rg1 * hn1);
        g_h[n * 64 + 32 + lane] = (1.f - zg1) * ng1 + zg1 * hB[r];
    }
}

// ---------------------------------------------------------------------------
// K4: z1 = relu(hperm @ W1^T + b1). hperm[bs, (e*G+g)*HC+f] = h[bs,g,e,f].
// ---------------------------------------------------------------------------
__global__ void k_mlp1(const float* __restrict__ W1, const float* __restrict__ b1) {
    __shared__ float W1s[128 * 65];
    __shared__ float hs[4 * 128];
    int tid = threadIdx.x;
    int bs0 = blockIdx.x * 4;
    int b_l = tid >> 6, o = tid & 63;
    float acc = 0.f;

    for (int kb = 0; kb < NG * NEL * HCC; kb += 128) {
        __syncthreads();
        for (int i = tid; i < 64 * 128; i += 256) {
            int ol = i >> 7, kl = i & 127;
            W1s[kl * 65 + ol] = W1[(size_t)ol * (NG * NEL * HCC) + kb + kl];
        }
        for (int i = tid; i < 4 * 128; i += 256) {
            int bl = i >> 7, kl = i & 127;
            int in = kb + kl;
            int f = in & 63;
            int t2 = in >> 6;
            int g = t2 % NG, e = t2 / NG;
            hs[bl * 128 + kl] = g_h[((((bs0 + bl) * NG + g) * NEL + e) * HCC) + f];
        }
        __syncthreads();
#pragma unroll 8
        for (int kk = 0; kk < 128; kk++)
            acc += W1s[kk * 65 + o] * hs[b_l * 128 + kk];
    }
    acc += b1[o];
    g_z1[(bs0 + b_l) * 64 + o] = fmaxf(acc, 0.f);
}

// ---------------------------------------------------------------------------
// K5: tail MLP (64->32->16->3) + softmax. One warp per batch row.
// ---------------------------------------------------------------------------
__global__ void k_tail(const float* __restrict__ W2, const float* __restrict__ b2,
                       const float* __restrict__ W3, const float* __restrict__ b3,
                       const float* __restrict__ W4, const float* __restrict__ b4,
                       float* __restrict__ out) {
    __shared__ float W2s[64 * 32], W3s[32 * 16], W4s[16 * 3];
    __shared__ float b2s[32], b3s[16], b4s[3];
    int tid = threadIdx.x;
    for (int i = tid; i < 32 * 64; i += 256) { int o = i >> 6, k = i & 63; W2s[k * 32 + o] = W2[i]; }
    for (int i = tid; i < 16 * 32; i += 256) { int o = i >> 5, k = i & 31; W3s[k * 16 + o] = W3[i]; }
    for (int i = tid; i < 3 * 16;  i += 256) { int o = i >> 4, k = i & 15; W4s[k * 3 + o] = W4[i]; }
    if (tid < 32) b2s[tid] = b2[tid];
    if (tid < 16) b3s[tid] = b3[tid];
    if (tid < 3)  b4s[tid] = b4[tid];
    __syncthreads();

    int lane = tid & 31, wp = tid >> 5;
    int bs = blockIdx.x * 8 + wp;
    float l0 = g_z1[bs * 64 + lane];
    float l1 = g_z1[bs * 64 + 32 + lane];

    float acc2 = b2s[lane];
#pragma unroll
    for (int i = 0; i < 32; i++) acc2 += __shfl_sync(0xffffffffu, l0, i) * W2s[i * 32 + lane];
#pragma unroll
    for (int i = 0; i < 32; i++) acc2 += __shfl_sync(0xffffffffu, l1, i) * W2s[(i + 32) * 32 + lane];
    float z2 = fmaxf(acc2, 0.f);

    float acc3 = (lane < 16) ? b3s[lane] : 0.f;
#pragma unroll
    for (int i = 0; i < 32; i++) {
        float v = __shfl_sync(0xffffffffu, z2, i);
        if (lane < 16) acc3 += v * W3s[i * 16 + lane];
    }
    float z3 = fmaxf(acc3, 0.f);

    float accL = (lane < 3) ? b4s[lane] : 0.f;
#pragma unroll
    for (int i = 0; i < 16; i++) {
        float v = __shfl_sync(0xffffffffu, z3, i);
        if (lane < 3) accL += v * W4s[i * 3 + lane];
    }

    float L0 = __shfl_sync(0xffffffffu, accL, 0);
    float L1 = __shfl_sync(0xffffffffu, accL, 1);
    float L2 = __shfl_sync(0xffffffffu, accL, 2);
    float mx = fmaxf(L0, fmaxf(L1, L2));
    float e0 = expf(L0 - mx), e1 = expf(L1 - mx), e2 = expf(L2 - mx);
    float si = 1.f / (e0 + e1 + e2);
    if (lane == 0) {
        out[bs * 3 + 0] = e0 * si;
        out[bs * 3 + 1] = e1 * si;
        out[bs * 3 + 2] = e2 * si;
    }
}

// ---------------------------------------------------------------------------
extern "C" void kernel_launch(void* const* d_in, const int* in_sizes, int n_in,
                              void* d_out, int out_size) {
    const float* x     = (const float*)d_in[0];
    const int*   ei    = (const int*)  d_in[1];
    const float* ea    = (const float*)d_in[2];
    const float* Wg    = (const float*)d_in[3];
    const float* w_ih  = (const float*)d_in[4];
    const float* w_hh  = (const float*)d_in[5];
    const float* b_ih  = (const float*)d_in[6];
    const float* b_hh  = (const float*)d_in[7];
    const float* W1    = (const float*)d_in[8];
    const float* b1    = (const float*)d_in[9];
    const float* W2    = (const float*)d_in[10];
    const float* b2    = (const float*)d_in[11];
    const float* W3    = (const float*)d_in[12];
    const float* b3    = (const float*)d_in[13];
    const float* W4    = (const float*)d_in[14];
    const float* b4    = (const float*)d_in[15];
    float* out = (float*)d_out;

    const size_t gru_smem = (size_t)(2 * 64 * KP * 2 + 2 * 192) * sizeof(float);
    cudaFuncSetAttribute(k_gru, cudaFuncAttributeMaxDynamicSharedMemorySize, (int)gru_smem);

    k_init<<<NN * HCC / 256, 256>>>(x);

    // CSR build (once per launch; reused by both layers)
    k_zero_deg<<<(NN + 255) / 256, 256>>>();
    k_count<<<(EE + 255) / 256, 256>>>(ei);
    k_scan1<<<NN / 1024, 1024>>>();
    k_scan2<<<1, 32>>>();
    k_scan3<<<(NN + 255) / 256, 256>>>();
    k_fill<<<(EE + 255) / 256, 256>>>(ei, ea);

    for (int layer = 0; layer < 2; layer++) {
        k_matmul<<<NN / 32, 256>>>(Wg + layer * HCC * HCC);
        k_gather<<<NN / 8, 256>>>();
        k_gru<<<NN / 64, 512, gru_smem>>>(w_ih, w_hh, b_ih, b_hh);
    }
    k_mlp1<<<BSZ / 4, 256>>>(W1, b1);
    k_tail<<<BSZ / 8, 256>>>(W2, b2, W3, b3, W4, b4, out);
}